// round 1
// baseline (speedup 1.0000x reference)
#include <cuda_runtime.h>
#include <math.h>

#define NN    20000
#define NEDGE 320000

// ---------------- device scratch (static, no allocs) ----------------
__device__ __align__(16) float g_s_up[NN * 64];     // s after up-proj      [n][c]
__device__ __align__(16) float g_v_up[NN * 192];    // v after up-proj      [n][c*3+m]
__device__ __align__(16) float g_msg_s[NN * 128];   // scalar messages      [n][128]
__device__ __align__(16) float g_msg_v[NN * 768];   // vector messages      [n][row*4 + m], m<3, pad

__device__ __forceinline__ void red4(float* p, float a, float b, float c, float d) {
    asm volatile("red.global.add.v4.f32 [%0], {%1,%2,%3,%4};"
                 :: "l"(p), "f"(a), "f"(b), "f"(c), "f"(d) : "memory");
}

__device__ __forceinline__ float silu_n(float y, float cs) {
    return cs * y * (1.f / (1.f + __expf(-y)));
}

// ---------------- kernel A: node up-projection ----------------
__global__ void node_up_kernel(const float* __restrict__ nf,
                               const float* __restrict__ Wup0,
                               const float* __restrict__ Wup1) {
    __shared__ float sW0[4096];
    __shared__ float sW1[4096];
    __shared__ float sIn[256];
    int t = threadIdx.x;
    for (int i = t; i < 4096; i += 256) {
        sW0[i] = Wup0[i] * 0.125f;   // * 1/sqrt(C)
        sW1[i] = Wup1[i] * 0.125f;
    }
    __syncthreads();
    int base = blockIdx.x * 8;
    for (int nn = 0; nn < 8; nn++) {
        int n = base + nn;
        sIn[t] = nf[n * 256 + t];
        __syncthreads();
        if (t < 64) {
            float acc = 0.f;
#pragma unroll 16
            for (int c = 0; c < 64; c++) acc = fmaf(sIn[c], sW0[c * 64 + t], acc);
            g_s_up[n * 64 + t] = acc;
        } else {
            int k = (t - 64) / 3, m = (t - 64) - 3 * k;
            float acc = 0.f;
#pragma unroll 16
            for (int c = 0; c < 64; c++) acc = fmaf(sIn[64 + c * 3 + m], sW1[c * 64 + k], acc);
            g_v_up[n * 192 + k * 3 + m] = acc;
        }
        __syncthreads();
    }
}

// ---------------- zero the message accumulators ----------------
__global__ void zero_msg_kernel() {
    int idx = blockIdx.x * blockDim.x + threadIdx.x;
    int stride = gridDim.x * blockDim.x;
    float4 z = make_float4(0.f, 0.f, 0.f, 0.f);
    for (int k = idx; k < NN * 128 / 4; k += stride) ((float4*)g_msg_s)[k] = z;
    for (int k = idx; k < NN * 768 / 4; k += stride) ((float4*)g_msg_v)[k] = z;
}

// ---------------- kernel E: edge MLP + messages + scatter ----------------
#define BCAST(h, i) __shfl_sync(0xffffffffu, (((i) & 1) ? (h).y : (h).x), (i) >> 1)

__device__ __forceinline__ void do_messages(int e, int lane, const float* tw,
                                            const float* __restrict__ ea,
                                            const int* __restrict__ ie,
                                            const int* __restrict__ je) {
    const float INV_SQRT3 = 0.5773502691896258f;
    const float INV_SQRT2 = 0.7071067811865476f;
    int inode = __ldg(&ie[e]);
    int jnode = __ldg(&je[e]);
    float4 e4 = *(const float4*)&ea[e * 4];
    float eas = e4.x, v0e = e4.y, v1e = e4.z, v2e = e4.w;
    const float* su = g_s_up + inode * 64;
    const float* vu = g_v_up + inode * 192;
    float* ms = g_msg_s + jnode * 128;
    float* mv = g_msg_v + jnode * 768;

    if (lane < 16) {
        // m0: channels 4l..4l+3
        int c = 4 * lane;
        float4 xs = *(const float4*)(su + c);
        red4(ms + c, tw[c] * xs.x * eas, tw[c + 1] * xs.y * eas,
                     tw[c + 2] * xs.z * eas, tw[c + 3] * xs.w * eas);
    } else {
        // m1: channels 4k..4k+3
        int k = lane - 16;
        int c = 4 * k;
        const float* vp = vu + c * 3;
        float4 p0 = *(const float4*)(vp);
        float4 p1 = *(const float4*)(vp + 4);
        float4 p2 = *(const float4*)(vp + 8);
        float d0 = p0.x * v0e + p0.y * v1e + p0.z * v2e;
        float d1 = p0.w * v0e + p1.x * v1e + p1.y * v2e;
        float d2 = p1.z * v0e + p1.w * v1e + p2.x * v2e;
        float d3 = p2.y * v0e + p2.z * v1e + p2.w * v2e;
        red4(ms + 64 + c, tw[64 + c] * d0 * INV_SQRT3, tw[64 + c + 1] * d1 * INV_SQRT3,
                          tw[64 + c + 2] * d2 * INV_SQRT3, tw[64 + c + 3] * d3 * INV_SQRT3);
    }
    // vector messages: rows 6l..6l+5 of [192][4] padded layout
#pragma unroll
    for (int rr = 0; rr < 6; rr++) {
        int row = 6 * lane + rr;
        float o0, o1, o2;
        if (row < 64) {                      // m2
            float tmp = tw[128 + row] * su[row];
            o0 = tmp * v0e; o1 = tmp * v1e; o2 = tmp * v2e;
        } else if (row < 128) {              // m3
            int c = row - 64;
            float w = tw[192 + c] * eas;
            o0 = w * vu[3 * c]; o1 = w * vu[3 * c + 1]; o2 = w * vu[3 * c + 2];
        } else {                             // m4: cross(xv, eav)/sqrt2
            int c = row - 128;
            float w = tw[256 + c] * INV_SQRT2;
            float x0 = vu[3 * c], x1 = vu[3 * c + 1], x2 = vu[3 * c + 2];
            o0 = w * (x1 * v2e - x2 * v1e);
            o1 = w * (x2 * v0e - x0 * v2e);
            o2 = w * (x0 * v1e - x1 * v0e);
        }
        red4(mv + row * 4, o0, o1, o2, 0.f);
    }
}

__global__ void __launch_bounds__(512, 1) edge_kernel(
    const float* __restrict__ ef, const float* __restrict__ ea,
    const int* __restrict__ ie, const int* __restrict__ je,
    const float* __restrict__ Wm1, const float* __restrict__ Wm2,
    const float* __restrict__ Wm3, const float* __restrict__ Wm4, float cs) {
    extern __shared__ float sh[];
    float* sW1 = sh;            // 512
    float* sW2 = sh + 512;      // 4096
    float* sW3 = sh + 4608;     // 4096
    float* sW4 = sh + 8704;     // 20480
    float* sT  = sh + 29184;    // 16 warps * 320
    int t = threadIdx.x;
    for (int i = t; i < 512; i += 512)   sW1[i] = Wm1[i] * 0.3535533905932738f;  // 1/sqrt(8)
    for (int i = t; i < 4096; i += 512) { sW2[i] = Wm2[i] * 0.125f; sW3[i] = Wm3[i] * 0.125f; }
    for (int i = t; i < 20480; i += 512) sW4[i] = Wm4[i] * 0.125f;
    __syncthreads();

    int lane = t & 31;
    int wIn = t >> 5;
    float* tw = sT + wIn * 320;
    int gw = blockIdx.x * 16 + wIn;
    int nw = gridDim.x * 16;

    for (int p = gw; p < NEDGE / 2; p += nw) {
        int e0 = 2 * p, e1 = 2 * p + 1;
        // ---- layer 1: 8 -> 64 ----
        float efr = 0.f;
        if (lane < 16) {
            int e = (lane < 8) ? e0 : e1;
            efr = ef[e * 8 + (lane & 7)];
        }
        float2 a0 = make_float2(0.f, 0.f), a1 = make_float2(0.f, 0.f);
#pragma unroll
        for (int i = 0; i < 8; i++) {
            float b0 = __shfl_sync(0xffffffffu, efr, i);
            float b1 = __shfl_sync(0xffffffffu, efr, 8 + i);
            float2 w = *(const float2*)&sW1[i * 64 + 2 * lane];
            a0.x = fmaf(b0, w.x, a0.x); a0.y = fmaf(b0, w.y, a0.y);
            a1.x = fmaf(b1, w.x, a1.x); a1.y = fmaf(b1, w.y, a1.y);
        }
        float2 h0, h1;
        h0.x = silu_n(a0.x, cs); h0.y = silu_n(a0.y, cs);
        h1.x = silu_n(a1.x, cs); h1.y = silu_n(a1.y, cs);
        // ---- layer 2: 64 -> 64 ----
        a0 = make_float2(0.f, 0.f); a1 = make_float2(0.f, 0.f);
#pragma unroll 8
        for (int i = 0; i < 64; i++) {
            float b0 = BCAST(h0, i);
            float b1 = BCAST(h1, i);
            float2 w = *(const float2*)&sW2[i * 64 + 2 * lane];
            a0.x = fmaf(b0, w.x, a0.x); a0.y = fmaf(b0, w.y, a0.y);
            a1.x = fmaf(b1, w.x, a1.x); a1.y = fmaf(b1, w.y, a1.y);
        }
        h0.x = silu_n(a0.x, cs); h0.y = silu_n(a0.y, cs);
        h1.x = silu_n(a1.x, cs); h1.y = silu_n(a1.y, cs);
        // ---- layer 3: 64 -> 64 ----
        a0 = make_float2(0.f, 0.f); a1 = make_float2(0.f, 0.f);
#pragma unroll 8
        for (int i = 0; i < 64; i++) {
            float b0 = BCAST(h0, i);
            float b1 = BCAST(h1, i);
            float2 w = *(const float2*)&sW3[i * 64 + 2 * lane];
            a0.x = fmaf(b0, w.x, a0.x); a0.y = fmaf(b0, w.y, a0.y);
            a1.x = fmaf(b1, w.x, a1.x); a1.y = fmaf(b1, w.y, a1.y);
        }
        h0.x = silu_n(a0.x, cs); h0.y = silu_n(a0.y, cs);
        h1.x = silu_n(a1.x, cs); h1.y = silu_n(a1.y, cs);
        // ---- layer 4: 64 -> 320 ----
        float2 t0[5], t1[5];
#pragma unroll
        for (int g = 0; g < 5; g++) { t0[g] = make_float2(0.f, 0.f); t1[g] = make_float2(0.f, 0.f); }
#pragma unroll 4
        for (int i = 0; i < 64; i++) {
            float b0 = BCAST(h0, i);
            float b1 = BCAST(h1, i);
#pragma unroll
            for (int g = 0; g < 5; g++) {
                float2 w = *(const float2*)&sW4[i * 320 + g * 64 + 2 * lane];
                t0[g].x = fmaf(b0, w.x, t0[g].x); t0[g].y = fmaf(b0, w.y, t0[g].y);
                t1[g].x = fmaf(b1, w.x, t1[g].x); t1[g].y = fmaf(b1, w.y, t1[g].y);
            }
        }
        // ---- messages for both edges ----
#pragma unroll
        for (int r = 0; r < 2; r++) {
#pragma unroll
            for (int g = 0; g < 5; g++)
                *(float2*)&tw[g * 64 + 2 * lane] = r ? t1[g] : t0[g];
            __syncwarp();
            do_messages(r ? e1 : e0, lane, tw, ea, ie, je);
            __syncwarp();
        }
    }
}

// ---------------- kernel F: node finalize ----------------
__global__ void __launch_bounds__(512, 1) finalize_kernel(
    const float* __restrict__ Wl0, const float* __restrict__ Wl1,
    const float* __restrict__ Ws0c1, const float* __restrict__ Ws0c2,
    const float* __restrict__ Ws0c3, const float* __restrict__ Ws1c1,
    const float* __restrict__ Ws1c2, const float* __restrict__ Ws1c3,
    const float* __restrict__ Wp0, const float* __restrict__ Wp1,
    const int* __restrict__ zn, float* __restrict__ out) {
    const float INV_SQRT3 = 0.5773502691896258f;
    const float INV_SQRT_2C = 0.08838834764831845f;   // 1/sqrt(128)
    const float INV_SQRT_3C = 0.07216878364870323f;   // 1/sqrt(192)
    extern __shared__ float sh[];
    float* sL0 = sh;              // 8192
    float* sL1 = sh + 8192;       // 12288
    float* sP0 = sh + 20480;      // 4096
    float* sP1 = sh + 24576;      // 4096
    float* sT01 = sh + 28672;     // 640
    float* sT02 = sh + 29312;     // 1280
    float* sT03 = sh + 30592;     // 1280
    float* sT11 = sh + 31872;     // 640
    float* sT12 = sh + 32512;     // 640
    float* sT13 = sh + 33152;     // 1280
    float* sDyn = sh + 34432;     // 2 * 1472 staging

    int t = threadIdx.x;
    for (int i = t; i < 8192; i += 512)  sL0[i] = Wl0[i] * INV_SQRT_2C;
    for (int i = t; i < 12288; i += 512) sL1[i] = Wl1[i] * INV_SQRT_3C;
    for (int i = t; i < 4096; i += 512) { sP0[i] = Wp0[i] * 0.125f; sP1[i] = Wp1[i] * 0.125f; }
    for (int i = t; i < 640; i += 512) { sT01[i] = Ws0c1[i]; sT11[i] = Ws1c1[i]; sT12[i] = Ws1c2[i]; }
    for (int i = t; i < 1280; i += 512) { sT02[i] = Ws0c2[i]; sT03[i] = Ws0c3[i]; sT13[i] = Ws1c3[i]; }
    __syncthreads();

    int sub = t >> 8;
    int tt = t & 255;
    float* st = sDyn + sub * 1472;
    float* ms  = st;          // 128
    float* mvv = st + 128;    // 768
    float* s2s = st + 896;    // 64
    float* v2s = st + 960;    // 192
    float* oss = st + 1152;   // 64
    float* cfs = st + 1216;   // 64
    float* ovs = st + 1280;   // 192

    for (int p = blockIdx.x; p < NN / 2; p += gridDim.x) {
        int n = 2 * p + sub;
        if (tt < 128) ms[tt] = g_msg_s[n * 128 + tt];
#pragma unroll
        for (int i = 0; i < 3; i++) mvv[tt + i * 256] = g_msg_v[n * 768 + tt + i * 256];
        __syncthreads();
        if (tt < 64) {
            float acc = 0.f;
#pragma unroll 8
            for (int c = 0; c < 128; c++) acc = fmaf(ms[c], sL0[c * 64 + tt], acc);
            s2s[tt] = acc;
        } else {
            int k = (tt - 64) / 3, m = (tt - 64) - 3 * k;
            float acc = 0.f;
#pragma unroll 8
            for (int r = 0; r < 192; r++) acc = fmaf(mvv[r * 4 + m], sL1[r * 64 + k], acc);
            v2s[k * 3 + m] = acc;
        }
        __syncthreads();
        if (tt < 64) {
            int z = zn[n];
            int k = tt;
            float s2 = s2s[k];
            float a = v2s[3 * k], b = v2s[3 * k + 1], c = v2s[3 * k + 2];
            float vvs = (a * a + b * b + c * c) * INV_SQRT3;
            float s22 = s2 * s2;
            float outs = sT01[z * 64 + k] * s2 + sT02[(2 * z) * 64 + k] * s22
                       + sT02[(2 * z + 1) * 64 + k] * vvs
                       + sT03[(2 * z) * 64 + k] * s22 * s2
                       + sT03[(2 * z + 1) * 64 + k] * s2 * vvs;
            float coef = sT11[z * 64 + k] + sT12[z * 64 + k] * s2
                       + sT13[(2 * z) * 64 + k] * s22 + sT13[(2 * z + 1) * 64 + k] * vvs;
            oss[k] = outs;
            cfs[k] = coef;
        }
        __syncthreads();
        if (tt >= 64) {
            int idx = tt - 64;
            int k = idx / 3;
            ovs[idx] = cfs[k] * v2s[idx];
        }
        __syncthreads();
        if (tt < 64) {
            float acc = 0.f;
#pragma unroll 8
            for (int c = 0; c < 64; c++) acc = fmaf(oss[c], sP0[c * 64 + tt], acc);
            out[n * 256 + tt] = acc;
        } else {
            int idx = tt - 64;
            int k = idx / 3, m = idx - 3 * k;
            float acc = 0.f;
#pragma unroll 8
            for (int c = 0; c < 64; c++) acc = fmaf(ovs[c * 3 + m], sP1[c * 64 + k], acc);
            out[n * 256 + 64 + idx] = acc;
        }
        __syncthreads();
    }
}

// ---------------- host launcher ----------------
extern "C" void kernel_launch(void* const* d_in, const int* in_sizes, int n_in,
                              void* d_out, int out_size) {
    const float* nf   = (const float*)d_in[0];
    const float* ef   = (const float*)d_in[1];
    const float* ea   = (const float*)d_in[2];
    const int*   ie   = (const int*)d_in[3];
    const int*   je   = (const int*)d_in[4];
    const int*   zn   = (const int*)d_in[5];
    const float* Wup0 = (const float*)d_in[6];
    const float* Wup1 = (const float*)d_in[7];
    const float* Wm1  = (const float*)d_in[8];
    const float* Wm2  = (const float*)d_in[9];
    const float* Wm3  = (const float*)d_in[10];
    const float* Wm4  = (const float*)d_in[11];
    const float* Wl0  = (const float*)d_in[12];
    const float* Wl1  = (const float*)d_in[13];
    const float* Ws0c1 = (const float*)d_in[14];
    const float* Ws0c2 = (const float*)d_in[15];
    const float* Ws0c3 = (const float*)d_in[16];
    const float* Ws1c1 = (const float*)d_in[17];
    const float* Ws1c2 = (const float*)d_in[18];
    const float* Ws1c3 = (const float*)d_in[19];
    const float* Wp0  = (const float*)d_in[20];
    const float* Wp1  = (const float*)d_in[21];
    float* out = (float*)d_out;

    // C_SILU = 1/sqrt(E_{z~N(0,1)}[silu(z)^2]) via trapezoid on R (exp. convergent)
    double m2 = 0.0;
    const double hstep = 1.0 / 128.0;
    for (int i = -14 * 128; i <= 14 * 128; i++) {
        double z = i * hstep;
        double f = z / (1.0 + exp(-z));
        m2 += exp(-0.5 * z * z) * f * f;
    }
    m2 *= hstep / sqrt(2.0 * 3.141592653589793);
    float cs = (float)(1.0 / sqrt(m2));

    cudaFuncSetAttribute(edge_kernel, cudaFuncAttributeMaxDynamicSharedMemorySize, 137216);
    cudaFuncSetAttribute(finalize_kernel, cudaFuncAttributeMaxDynamicSharedMemorySize, 149504);

    node_up_kernel<<<2500, 256>>>(nf, Wup0, Wup1);
    zero_msg_kernel<<<2048, 256>>>();
    edge_kernel<<<296, 512, 137216>>>(ef, ea, ie, je, Wm1, Wm2, Wm3, Wm4, cs);
    finalize_kernel<<<296, 512, 149504>>>(Wl0, Wl1, Ws0c1, Ws0c2, Ws0c3,
                                          Ws1c1, Ws1c2, Ws1c3, Wp0, Wp1, zn, out);
}

// round 2
// speedup vs baseline: 1.2441x; 1.2441x over previous
#include <cuda_runtime.h>
#include <math.h>

#define NN    20000
#define NEDGE 320000

// ---------------- device scratch (static, no allocs) ----------------
__device__ __align__(16) float g_s_up[NN * 64];
__device__ __align__(16) float g_v_up[NN * 192];
__device__ __align__(16) float g_msg_s[NN * 128];
__device__ __align__(16) float g_msg_v[NN * 768];           // [n][row*4+m]
__device__ __align__(16) float g_tpw[(size_t)NEDGE * 320];  // edge MLP output
__device__ __align__(16) unsigned g_wfrag[29184];           // tf32 fragment weights

__device__ __forceinline__ void red4(float* p, float a, float b, float c, float d) {
    asm volatile("red.global.add.v4.f32 [%0], {%1,%2,%3,%4};"
                 :: "l"(p), "f"(a), "f"(b), "f"(c), "f"(d) : "memory");
}
__device__ __forceinline__ float silu_n(float y, float cs) {
    return cs * y * (1.f / (1.f + __expf(-y)));
}
__device__ __forceinline__ unsigned f2tf(float x) {
    unsigned r; asm("cvt.rna.tf32.f32 %0, %1;" : "=r"(r) : "f"(x)); return r;
}
__device__ __forceinline__ void mma8(float* c, const unsigned* a, unsigned b0, unsigned b1) {
    asm volatile("mma.sync.aligned.m16n8k8.row.col.f32.tf32.tf32.f32 "
                 "{%0,%1,%2,%3}, {%4,%5,%6,%7}, {%8,%9}, {%0,%1,%2,%3};"
                 : "+f"(c[0]), "+f"(c[1]), "+f"(c[2]), "+f"(c[3])
                 : "r"(a[0]), "r"(a[1]), "r"(a[2]), "r"(a[3]), "r"(b0), "r"(b1));
}

// ---------------- kernel A: node up-projection ----------------
__global__ void node_up_kernel(const float* __restrict__ nf,
                               const float* __restrict__ Wup0,
                               const float* __restrict__ Wup1) {
    __shared__ float sW0[4096];
    __shared__ float sW1[4096];
    __shared__ float sIn[256];
    int t = threadIdx.x;
    for (int i = t; i < 4096; i += 256) {
        sW0[i] = Wup0[i] * 0.125f;
        sW1[i] = Wup1[i] * 0.125f;
    }
    __syncthreads();
    int base = blockIdx.x * 8;
    for (int nn = 0; nn < 8; nn++) {
        int n = base + nn;
        sIn[t] = nf[n * 256 + t];
        __syncthreads();
        if (t < 64) {
            float acc = 0.f;
#pragma unroll 16
            for (int c = 0; c < 64; c++) acc = fmaf(sIn[c], sW0[c * 64 + t], acc);
            g_s_up[n * 64 + t] = acc;
        } else {
            int k = (t - 64) / 3, m = (t - 64) - 3 * k;
            float acc = 0.f;
#pragma unroll 16
            for (int c = 0; c < 64; c++) acc = fmaf(sIn[64 + c * 3 + m], sW1[c * 64 + k], acc);
            g_v_up[n * 192 + k * 3 + m] = acc;
        }
        __syncthreads();
    }
}

// ---------------- zero message accumulators ----------------
__global__ void zero_msg_kernel() {
    int idx = blockIdx.x * blockDim.x + threadIdx.x;
    int stride = gridDim.x * blockDim.x;
    float4 z = make_float4(0.f, 0.f, 0.f, 0.f);
    for (int k = idx; k < NN * 128 / 4; k += stride) ((float4*)g_msg_s)[k] = z;
    for (int k = idx; k < NN * 768 / 4; k += stride) ((float4*)g_msg_v)[k] = z;
}

// ---------------- weight fragment prep (tf32, prescaled) ----------------
// layout: W1f @0 (1x8 tiles), W2f @512 (8x8), W3f @4608 (8x8), W4f @8704 (8x40)
// per (kt,nt): 32 lanes x 2 regs: b0=W[kt*8+tg][nt*8+g], b1=W[kt*8+tg+4][nt*8+g]
__global__ void wprep_kernel(const float* __restrict__ W1, const float* __restrict__ W2,
                             const float* __restrict__ W3, const float* __restrict__ W4) {
    int p = blockIdx.x * blockDim.x + threadIdx.x;
    if (p >= 14592) return;
    const float* W; int NT, Ncols, base, off; float scale;
    if (p < 256)       { W = W1; NT = 8;  Ncols = 64;  base = 0;    off = p;        scale = 0.3535533905932738f; }
    else if (p < 2304) { W = W2; NT = 8;  Ncols = 64;  base = 512;  off = p - 256;  scale = 0.125f; }
    else if (p < 4352) { W = W3; NT = 8;  Ncols = 64;  base = 4608; off = p - 2304; scale = 0.125f; }
    else               { W = W4; NT = 40; Ncols = 320; base = 8704; off = p - 4352; scale = 0.125f; }
    int lane = off & 31, ktnt = off >> 5;
    int nt = ktnt % NT, kt = ktnt / NT;
    int g = lane >> 2, tg = lane & 3;
    float b0 = W[(kt * 8 + tg) * Ncols + nt * 8 + g] * scale;
    float b1 = W[(kt * 8 + tg + 4) * Ncols + nt * 8 + g] * scale;
    g_wfrag[base + off * 2]     = f2tf(b0);
    g_wfrag[base + off * 2 + 1] = f2tf(b1);
}

// ---------------- edge MLP via tf32 tensor cores ----------------
// 32 edges per warp, 8 warps per block, 256 edges/block, grid 1250.
// h staging: 32 rows x 68 floats per warp (stride 68 -> conflict-free A frags)
__global__ void __launch_bounds__(256, 1) mlp_kernel(const float* __restrict__ ef, float cs) {
    extern __shared__ float sh[];
    unsigned* wf = (unsigned*)sh;                 // 29184 u32
    int t = threadIdx.x;
    for (int i = t; i < 29184; i += 256) wf[i] = g_wfrag[i];
    int warp = t >> 5, lane = t & 31, g = lane >> 2, tg = lane & 3;
    float* hb = sh + 29184 + warp * 2176;
    __syncthreads();
    int base = (blockIdx.x * 8 + warp) * 32;

    // stage ef [32 x 8]
    for (int i = lane; i < 256; i += 32) {
        int r = i >> 3, c = i & 7;
        hb[r * 68 + c] = ef[(base + r) * 8 + c];
    }
    __syncwarp();

    // ---- layer 1 (K=8) ----
    {
        unsigned A[2][4];
        float C[2][8][4];
#pragma unroll
        for (int mt = 0; mt < 2; mt++) {
            int r0 = mt * 16 + g;
            A[mt][0] = f2tf(hb[r0 * 68 + tg]);
            A[mt][1] = f2tf(hb[(r0 + 8) * 68 + tg]);
            A[mt][2] = f2tf(hb[r0 * 68 + tg + 4]);
            A[mt][3] = f2tf(hb[(r0 + 8) * 68 + tg + 4]);
#pragma unroll
            for (int nt = 0; nt < 8; nt++)
                C[mt][nt][0] = C[mt][nt][1] = C[mt][nt][2] = C[mt][nt][3] = 0.f;
        }
        __syncwarp();
#pragma unroll
        for (int nt = 0; nt < 8; nt++) {
            uint2 b = *(const uint2*)&wf[(nt * 32 + lane) * 2];
            mma8(C[0][nt], A[0], b.x, b.y);
            mma8(C[1][nt], A[1], b.x, b.y);
        }
#pragma unroll
        for (int mt = 0; mt < 2; mt++) {
            int r0 = mt * 16 + g;
#pragma unroll
            for (int nt = 0; nt < 8; nt++) {
                int col = nt * 8 + 2 * tg;
                hb[r0 * 68 + col]         = silu_n(C[mt][nt][0], cs);
                hb[r0 * 68 + col + 1]     = silu_n(C[mt][nt][1], cs);
                hb[(r0 + 8) * 68 + col]     = silu_n(C[mt][nt][2], cs);
                hb[(r0 + 8) * 68 + col + 1] = silu_n(C[mt][nt][3], cs);
            }
        }
        __syncwarp();
    }

    // ---- layers 2 and 3 (64 -> 64) ----
#pragma unroll 1
    for (int l = 0; l < 2; l++) {
        const unsigned* wl = wf + (l == 0 ? 512 : 4608);
        unsigned A[2][8][4];
#pragma unroll
        for (int mt = 0; mt < 2; mt++) {
            int r0 = mt * 16 + g;
#pragma unroll
            for (int kt = 0; kt < 8; kt++) {
                A[mt][kt][0] = f2tf(hb[r0 * 68 + kt * 8 + tg]);
                A[mt][kt][1] = f2tf(hb[(r0 + 8) * 68 + kt * 8 + tg]);
                A[mt][kt][2] = f2tf(hb[r0 * 68 + kt * 8 + tg + 4]);
                A[mt][kt][3] = f2tf(hb[(r0 + 8) * 68 + kt * 8 + tg + 4]);
            }
        }
        __syncwarp();
        float C[2][8][4];
#pragma unroll
        for (int mt = 0; mt < 2; mt++)
#pragma unroll
            for (int nt = 0; nt < 8; nt++)
                C[mt][nt][0] = C[mt][nt][1] = C[mt][nt][2] = C[mt][nt][3] = 0.f;
#pragma unroll
        for (int kt = 0; kt < 8; kt++) {
#pragma unroll
            for (int nt = 0; nt < 8; nt++) {
                uint2 b = *(const uint2*)&wl[((kt * 8 + nt) * 32 + lane) * 2];
                mma8(C[0][nt], A[0][kt], b.x, b.y);
                mma8(C[1][nt], A[1][kt], b.x, b.y);
            }
        }
#pragma unroll
        for (int mt = 0; mt < 2; mt++) {
            int r0 = mt * 16 + g;
#pragma unroll
            for (int nt = 0; nt < 8; nt++) {
                int col = nt * 8 + 2 * tg;
                hb[r0 * 68 + col]         = silu_n(C[mt][nt][0], cs);
                hb[r0 * 68 + col + 1]     = silu_n(C[mt][nt][1], cs);
                hb[(r0 + 8) * 68 + col]     = silu_n(C[mt][nt][2], cs);
                hb[(r0 + 8) * 68 + col + 1] = silu_n(C[mt][nt][3], cs);
            }
        }
        __syncwarp();
    }

    // ---- layer 4 (64 -> 320), output straight to g_tpw ----
#pragma unroll 1
    for (int mt = 0; mt < 2; mt++) {
        int r0 = mt * 16 + g;
        unsigned A[8][4];
#pragma unroll
        for (int kt = 0; kt < 8; kt++) {
            A[kt][0] = f2tf(hb[r0 * 68 + kt * 8 + tg]);
            A[kt][1] = f2tf(hb[(r0 + 8) * 68 + kt * 8 + tg]);
            A[kt][2] = f2tf(hb[r0 * 68 + kt * 8 + tg + 4]);
            A[kt][3] = f2tf(hb[(r0 + 8) * 68 + kt * 8 + tg + 4]);
        }
#pragma unroll 1
        for (int chunk = 0; chunk < 5; chunk++) {
            float C[8][4];
#pragma unroll
            for (int nt = 0; nt < 8; nt++)
                C[nt][0] = C[nt][1] = C[nt][2] = C[nt][3] = 0.f;
#pragma unroll
            for (int kt = 0; kt < 8; kt++) {
#pragma unroll
                for (int nt = 0; nt < 8; nt++) {
                    uint2 b = *(const uint2*)&wf[8704 + ((kt * 40 + chunk * 8 + nt) * 32 + lane) * 2];
                    mma8(C[nt], A[kt], b.x, b.y);
                }
            }
#pragma unroll
            for (int nt = 0; nt < 8; nt++) {
                int col = (chunk * 8 + nt) * 8 + 2 * tg;
                *(float2*)&g_tpw[(size_t)(base + r0) * 320 + col]     = make_float2(C[nt][0], C[nt][1]);
                *(float2*)&g_tpw[(size_t)(base + r0 + 8) * 320 + col] = make_float2(C[nt][2], C[nt][3]);
            }
        }
    }
}

// ---------------- messages + scatter ----------------
__device__ __forceinline__ void do_messages(int e, int lane, const float* __restrict__ tw,
                                            const float* __restrict__ ea,
                                            const int* __restrict__ ie,
                                            const int* __restrict__ je) {
    const float INV_SQRT3 = 0.5773502691896258f;
    const float INV_SQRT2 = 0.7071067811865476f;
    int inode = __ldg(&ie[e]);
    int jnode = __ldg(&je[e]);
    float4 e4 = *(const float4*)&ea[e * 4];
    float eas = e4.x, v0e = e4.y, v1e = e4.z, v2e = e4.w;
    const float* su = g_s_up + inode * 64;
    const float* vu = g_v_up + inode * 192;
    float* ms = g_msg_s + jnode * 128;
    float* mv = g_msg_v + jnode * 768;

    if (lane < 16) {
        int c = 4 * lane;
        float4 xs = *(const float4*)(su + c);
        red4(ms + c, tw[c] * xs.x * eas, tw[c + 1] * xs.y * eas,
                     tw[c + 2] * xs.z * eas, tw[c + 3] * xs.w * eas);
    } else {
        int k = lane - 16;
        int c = 4 * k;
        const float* vp = vu + c * 3;
        float4 p0 = *(const float4*)(vp);
        float4 p1 = *(const float4*)(vp + 4);
        float4 p2 = *(const float4*)(vp + 8);
        float d0 = p0.x * v0e + p0.y * v1e + p0.z * v2e;
        float d1 = p0.w * v0e + p1.x * v1e + p1.y * v2e;
        float d2 = p1.z * v0e + p1.w * v1e + p2.x * v2e;
        float d3 = p2.y * v0e + p2.z * v1e + p2.w * v2e;
        red4(ms + 64 + c, tw[64 + c] * d0 * INV_SQRT3, tw[64 + c + 1] * d1 * INV_SQRT3,
                          tw[64 + c + 2] * d2 * INV_SQRT3, tw[64 + c + 3] * d3 * INV_SQRT3);
    }
#pragma unroll
    for (int rr = 0; rr < 6; rr++) {
        int row = 6 * lane + rr;
        float o0, o1, o2;
        if (row < 64) {
            float tmp = tw[128 + row] * su[row];
            o0 = tmp * v0e; o1 = tmp * v1e; o2 = tmp * v2e;
        } else if (row < 128) {
            int c = row - 64;
            float w = tw[192 + c] * eas;
            o0 = w * vu[3 * c]; o1 = w * vu[3 * c + 1]; o2 = w * vu[3 * c + 2];
        } else {
            int c = row - 128;
            float w = tw[256 + c] * INV_SQRT2;
            float x0 = vu[3 * c], x1 = vu[3 * c + 1], x2 = vu[3 * c + 2];
            o0 = w * (x1 * v2e - x2 * v1e);
            o1 = w * (x2 * v0e - x0 * v2e);
            o2 = w * (x0 * v1e - x1 * v0e);
        }
        red4(mv + row * 4, o0, o1, o2, 0.f);
    }
}

__global__ void __launch_bounds__(512, 1) msg_kernel(const float* __restrict__ ea,
                                                     const int* __restrict__ ie,
                                                     const int* __restrict__ je) {
    int w = (blockIdx.x * 512 + threadIdx.x) >> 5;
    int lane = threadIdx.x & 31;
    int nw = (gridDim.x * 512) >> 5;
    for (int e = w; e < NEDGE; e += nw)
        do_messages(e, lane, g_tpw + (size_t)e * 320, ea, ie, je);
}

// ---------------- finalize: 2-node register blocking ----------------
__global__ void __launch_bounds__(512, 1) finalize_kernel(
    const float* __restrict__ Wl0, const float* __restrict__ Wl1,
    const float* __restrict__ Ws0c1, const float* __restrict__ Ws0c2,
    const float* __restrict__ Ws0c3, const float* __restrict__ Ws1c1,
    const float* __restrict__ Ws1c2, const float* __restrict__ Ws1c3,
    const float* __restrict__ Wp0, const float* __restrict__ Wp1,
    const int* __restrict__ zn, float* __restrict__ out) {
    const float INV_SQRT3 = 0.5773502691896258f;
    const float INV_SQRT_2C = 0.08838834764831845f;
    const float INV_SQRT_3C = 0.07216878364870323f;
    extern __shared__ float sh[];
    float* sL0 = sh;              // 8192
    float* sL1 = sh + 8192;       // 12288
    float* sP0 = sh + 20480;      // 4096
    float* sP1 = sh + 24576;      // 4096
    float* sT01 = sh + 28672;     // 640
    float* sT02 = sh + 29312;     // 1280
    float* sT03 = sh + 30592;     // 1280
    float* sT11 = sh + 31872;     // 640
    float* sT12 = sh + 32512;     // 640
    float* sT13 = sh + 33152;     // 1280
    float* sDyn = sh + 34432;     // 2 subgroups x 2816

    int t = threadIdx.x;
    for (int i = t; i < 8192; i += 512)  sL0[i] = Wl0[i] * INV_SQRT_2C;
    for (int i = t; i < 12288; i += 512) sL1[i] = Wl1[i] * INV_SQRT_3C;
    for (int i = t; i < 4096; i += 512) { sP0[i] = Wp0[i] * 0.125f; sP1[i] = Wp1[i] * 0.125f; }
    for (int i = t; i < 640; i += 512) { sT01[i] = Ws0c1[i]; sT11[i] = Ws1c1[i]; sT12[i] = Ws1c2[i]; }
    for (int i = t; i < 1280; i += 512) { sT02[i] = Ws0c2[i]; sT03[i] = Ws0c3[i]; sT13[i] = Ws1c3[i]; }
    __syncthreads();

    int sub = t >> 8;
    int tt = t & 255;
    float* st  = sDyn + sub * 2816;
    float* ms  = st;           // [2][128]
    float* mv  = st + 256;     // [2][768]
    float* v2s = st + 1792;    // [2][192]
    float* oss = st + 2176;    // [2][64]
    float* cfs = st + 2304;    // [2][64]
    float* ovs = st + 2432;    // [2][192]

    for (int p = blockIdx.x; p < NN / 4; p += gridDim.x) {
        int n0 = 4 * p + 2 * sub;
        // stage messages for 2 nodes
        ms[tt] = g_msg_s[(n0 + (tt >> 7)) * 128 + (tt & 127)];
#pragma unroll
        for (int i = 0; i < 6; i++) {
            int idx = i * 256 + tt;
            int nd = idx >= 768;
            mv[idx] = g_msg_v[(n0 + nd) * 768 + (idx - nd * 768)];
        }
        __syncthreads();

        float s2a = 0.f, s2b = 0.f;
        if (tt < 64) {
            int col = tt;
#pragma unroll 8
            for (int c = 0; c < 128; c++) {
                float w = sL0[c * 64 + col];
                s2a = fmaf(ms[c], w, s2a);
                s2b = fmaf(ms[128 + c], w, s2b);
            }
        } else {
            int k = (tt - 64) / 3, m = (tt - 64) - 3 * k;
            float a0 = 0.f, a1 = 0.f;
#pragma unroll 8
            for (int r = 0; r < 192; r++) {
                float w = sL1[r * 64 + k];
                a0 = fmaf(mv[r * 4 + m], w, a0);
                a1 = fmaf(mv[768 + r * 4 + m], w, a1);
            }
            v2s[k * 3 + m] = a0;
            v2s[192 + k * 3 + m] = a1;
        }
        __syncthreads();

        if (tt < 64) {
            int k = tt;
#pragma unroll
            for (int n = 0; n < 2; n++) {
                float s2 = n ? s2b : s2a;
                int z = zn[n0 + n];
                float a = v2s[n * 192 + 3 * k], b = v2s[n * 192 + 3 * k + 1], c = v2s[n * 192 + 3 * k + 2];
                float vv = (a * a + b * b + c * c) * INV_SQRT3;
                float s22 = s2 * s2;
                float outs = sT01[z * 64 + k] * s2 + sT02[(2 * z) * 64 + k] * s22
                           + sT02[(2 * z + 1) * 64 + k] * vv
                           + sT03[(2 * z) * 64 + k] * s22 * s2
                           + sT03[(2 * z + 1) * 64 + k] * s2 * vv;
                float coef = sT11[z * 64 + k] + sT12[z * 64 + k] * s2
                           + sT13[(2 * z) * 64 + k] * s22 + sT13[(2 * z + 1) * 64 + k] * vv;
                oss[n * 64 + k] = outs;
                cfs[n * 64 + k] = coef;
            }
        }
        __syncthreads();
        if (tt >= 64) {
            int idx = tt - 64;
            int k = idx / 3;
            ovs[idx]       = cfs[k] * v2s[idx];
            ovs[192 + idx] = cfs[64 + k] * v2s[192 + idx];
        }
        __syncthreads();

        if (tt < 64) {
            float a0 = 0.f, a1 = 0.f;
#pragma unroll 8
            for (int c = 0; c < 64; c++) {
                float w = sP0[c * 64 + tt];
                a0 = fmaf(oss[c], w, a0);
                a1 = fmaf(oss[64 + c], w, a1);
            }
            out[n0 * 256 + tt] = a0;
            out[(n0 + 1) * 256 + tt] = a1;
        } else {
            int idx = tt - 64;
            int k = idx / 3, m = idx - 3 * k;
            float a0 = 0.f, a1 = 0.f;
#pragma unroll 8
            for (int c = 0; c < 64; c++) {
                float w = sP1[c * 64 + k];
                a0 = fmaf(ovs[c * 3 + m], w, a0);
                a1 = fmaf(ovs[192 + c * 3 + m], w, a1);
            }
            out[n0 * 256 + 64 + idx] = a0;
            out[(n0 + 1) * 256 + 64 + idx] = a1;
        }
        __syncthreads();
    }
}

// ---------------- host launcher ----------------
extern "C" void kernel_launch(void* const* d_in, const int* in_sizes, int n_in,
                              void* d_out, int out_size) {
    const float* nf   = (const float*)d_in[0];
    const float* ef   = (const float*)d_in[1];
    const float* ea   = (const float*)d_in[2];
    const int*   ie   = (const int*)d_in[3];
    const int*   je   = (const int*)d_in[4];
    const int*   zn   = (const int*)d_in[5];
    const float* Wup0 = (const float*)d_in[6];
    const float* Wup1 = (const float*)d_in[7];
    const float* Wm1  = (const float*)d_in[8];
    const float* Wm2  = (const float*)d_in[9];
    const float* Wm3  = (const float*)d_in[10];
    const float* Wm4  = (const float*)d_in[11];
    const float* Wl0  = (const float*)d_in[12];
    const float* Wl1  = (const float*)d_in[13];
    const float* Ws0c1 = (const float*)d_in[14];
    const float* Ws0c2 = (const float*)d_in[15];
    const float* Ws0c3 = (const float*)d_in[16];
    const float* Ws1c1 = (const float*)d_in[17];
    const float* Ws1c2 = (const float*)d_in[18];
    const float* Ws1c3 = (const float*)d_in[19];
    const float* Wp0  = (const float*)d_in[20];
    const float* Wp1  = (const float*)d_in[21];
    float* out = (float*)d_out;

    // C_SILU via trapezoid on R (matches Gauss-Hermite to <1e-7)
    double m2 = 0.0;
    const double hstep = 1.0 / 128.0;
    for (int i = -14 * 128; i <= 14 * 128; i++) {
        double z = i * hstep;
        double f = z / (1.0 + exp(-z));
        m2 += exp(-0.5 * z * z) * f * f;
    }
    m2 *= hstep / sqrt(2.0 * 3.141592653589793);
    float cs = (float)(1.0 / sqrt(m2));

    cudaFuncSetAttribute(mlp_kernel, cudaFuncAttributeMaxDynamicSharedMemorySize, 186368);
    cudaFuncSetAttribute(finalize_kernel, cudaFuncAttributeMaxDynamicSharedMemorySize, 160256);

    node_up_kernel<<<2500, 256>>>(nf, Wup0, Wup1);
    zero_msg_kernel<<<2048, 256>>>();
    wprep_kernel<<<57, 256>>>(Wm1, Wm2, Wm3, Wm4);
    mlp_kernel<<<1250, 256, 186368>>>(ef, cs);
    msg_kernel<<<296, 512>>>(ea, ie, je);
    finalize_kernel<<<296, 512, 160256>>>(Wl0, Wl1, Ws0c1, Ws0c2, Ws0c3,
                                          Ws1c1, Ws1c2, Ws1c3, Wp0, Wp1, zn, out);
}